// round 4
// baseline (speedup 1.0000x reference)
#include <cuda_runtime.h>
#include <cstdint>
#include <math.h>

#define D_MODEL 768
#define D_INNER 768
#define D_STATE 8
#define BATCH 4
#define SEQ 8192
#define NTOK (BATCH*SEQ)          /* 32768 */
#define CHUNK 256
#define NCHUNK (SEQ/CHUNK)        /* 32 */

// -------- scratch (allocation-free: __device__ globals) --------
__device__ float g_XZ[(size_t)NTOK * 2 * D_INNER];   // in_proj output
__device__ float g_T [(size_t)NTOK * D_INNER];       // (localcum*BC+u*D)*silz, fixed in place
__device__ float g_SZ[(size_t)NTOK * D_INNER];       // silu(z)
__device__ float g_CHS[BATCH * NCHUNK * D_INNER];
__device__ float g_CBC[BATCH * NCHUNK * D_INNER];

// ================= TF32 GEMM (mma.sync m16n8k8) =================
// CTA tile 128x128, K-tile 32, double-buffered, 2 CTAs/SM.
#define BM 128
#define BN 128
#define BK 32
#define APAD 36    // A smem row stride (floats): 36%32=4 -> conflict-free a-frag loads
#define BPAD 136   // B smem row stride (floats): 136%32=8 -> conflict-free b-frag loads
#define A_ELE (BM * APAD)     /* 4608 floats = 18432 B per stage */
#define B_ELE (BK * BPAD)     /* 4352 floats = 17408 B per stage */
#define SMEM_FLOATS (2 * (A_ELE + B_ELE))   /* 17920 floats = 71680 B */

__device__ __forceinline__ uint32_t f2tf32(float f) {
    uint32_t u;
    asm("cvt.rna.tf32.f32 %0, %1;" : "=r"(u) : "f"(f));
    return u;
}

__device__ __forceinline__ void mma_tf32(float* d, const uint32_t* a, const uint32_t* b) {
    asm volatile(
        "mma.sync.aligned.m16n8k8.row.col.f32.tf32.tf32.f32 "
        "{%0,%1,%2,%3}, {%4,%5,%6,%7}, {%8,%9}, {%0,%1,%2,%3};"
        : "+f"(d[0]), "+f"(d[1]), "+f"(d[2]), "+f"(d[3])
        : "r"(a[0]), "r"(a[1]), "r"(a[2]), "r"(a[3]), "r"(b[0]), "r"(b[1]));
}

__device__ __forceinline__ void cp16(void* smem, const void* g) {
    uint32_t sa = (uint32_t)__cvta_generic_to_shared(smem);
    asm volatile("cp.async.cg.shared.global [%0], [%1], 16;" :: "r"(sa), "l"(g));
}

// asel: 0 -> A = Aext ; 1 -> A = g_T
// csel: 0 -> C = Cext ; 1 -> C = g_XZ
__global__ void __launch_bounds__(256, 2)
gemm_tf32(const float* __restrict__ Aext, const float* __restrict__ Bmat,
          float* __restrict__ Cext, int M, int N, int K, int asel, int csel)
{
    const float* __restrict__ A = asel ? g_T : Aext;
    float* __restrict__ C = csel ? g_XZ : Cext;

    extern __shared__ __align__(16) float smem[];
    float* sA[2] = { smem,            smem + A_ELE };
    float* sB[2] = { smem + 2*A_ELE,  smem + 2*A_ELE + B_ELE };

    const int tid  = threadIdx.x;
    const int warp = tid >> 5;
    const int lane = tid & 31;
    const int warpM = warp >> 2;       // 0..1   (warp tile 64 x 32)
    const int warpN = warp & 3;        // 0..3
    const int gid = lane >> 2;         // 0..7
    const int q   = lane & 3;          // 0..3

    const int bm = blockIdx.y * BM;
    const int bn = blockIdx.x * BN;

    float acc[4][4][4];
    #pragma unroll
    for (int mt = 0; mt < 4; ++mt)
        #pragma unroll
        for (int nt = 0; nt < 4; ++nt)
            #pragma unroll
            for (int i = 0; i < 4; ++i) acc[mt][nt][i] = 0.f;

    const int KT = K / BK;

    // --- async tile load: stage s, k-tile kt. 2048 x 16B chunks, 8/thread ---
    auto load_stage = [&](int s, int kt) {
        const float* Ag = A    + (size_t)bm * K + kt * BK;
        const float* Bg = Bmat + (size_t)kt * BK * N + bn;
        #pragma unroll
        for (int it = 0; it < 4; ++it) {
            int idx = it * 256 + tid;           // 0..1023
            int ar  = idx >> 3;                 // 0..127
            int ac4 = idx & 7;                  // 0..7
            cp16(&sA[s][ar * APAD + ac4 * 4], Ag + (size_t)ar * K + ac4 * 4);
            int br  = idx >> 5;                 // 0..31
            int bc4 = idx & 31;                 // 0..31
            cp16(&sB[s][br * BPAD + bc4 * 4], Bg + (size_t)br * N + bc4 * 4);
        }
    };

    load_stage(0, 0);
    asm volatile("cp.async.commit_group;");

    for (int kt = 0; kt < KT; ++kt) {
        asm volatile("cp.async.wait_group 0;");
        __syncthreads();
        if (kt + 1 < KT) {
            load_stage((kt + 1) & 1, kt + 1);
            asm volatile("cp.async.commit_group;");
        }
        const float* __restrict__ sAp = sA[kt & 1];
        const float* __restrict__ sBp = sB[kt & 1];

        #pragma unroll
        for (int k8 = 0; k8 < BK / 8; ++k8) {
            uint32_t af[4][4], bf[4][2];
            #pragma unroll
            for (int mt = 0; mt < 4; ++mt) {
                int r0 = warpM * 64 + mt * 16 + gid;
                af[mt][0] = f2tf32(sAp[(r0    ) * APAD + k8 * 8 + q    ]);
                af[mt][1] = f2tf32(sAp[(r0 + 8) * APAD + k8 * 8 + q    ]);
                af[mt][2] = f2tf32(sAp[(r0    ) * APAD + k8 * 8 + q + 4]);
                af[mt][3] = f2tf32(sAp[(r0 + 8) * APAD + k8 * 8 + q + 4]);
            }
            #pragma unroll
            for (int nt = 0; nt < 4; ++nt) {
                int cn = warpN * 32 + nt * 8 + gid;
                bf[nt][0] = f2tf32(sBp[(k8 * 8 + q    ) * BPAD + cn]);
                bf[nt][1] = f2tf32(sBp[(k8 * 8 + q + 4) * BPAD + cn]);
            }
            #pragma unroll
            for (int mt = 0; mt < 4; ++mt)
                #pragma unroll
                for (int nt = 0; nt < 4; ++nt)
                    mma_tf32(acc[mt][nt], af[mt], bf[nt]);
        }
    }

    // epilogue: direct stores (f32x2 per fragment pair)
    #pragma unroll
    for (int mt = 0; mt < 4; ++mt) {
        int gm = bm + warpM * 64 + mt * 16 + gid;
        #pragma unroll
        for (int nt = 0; nt < 4; ++nt) {
            int gn = bn + warpN * 32 + nt * 8 + q * 2;
            float2 v0 = make_float2(acc[mt][nt][0], acc[mt][nt][1]);
            float2 v1 = make_float2(acc[mt][nt][2], acc[mt][nt][3]);
            *(float2*)&C[(size_t)gm * N + gn]       = v0;
            *(float2*)&C[(size_t)(gm + 8) * N + gn] = v1;
        }
    }
}

// ============ Phase A: conv3 + silu + local cumsum per chunk ============
__global__ void __launch_bounds__(256)
scan_kernel(const float* __restrict__ conv_w, const float* __restrict__ conv_b,
            const float* __restrict__ Bm, const float* __restrict__ Cm,
            const float* __restrict__ Dv)
{
    const int d = blockIdx.x * 256 + threadIdx.x;
    const int c = blockIdx.y;
    const int b = blockIdx.z;

    const float w0 = conv_w[d * 3 + 0];
    const float w1 = conv_w[d * 3 + 1];
    const float w2 = conv_w[d * 3 + 2];
    const float cb = conv_b[d];
    float bc = 0.f;
    #pragma unroll
    for (int s = 0; s < D_STATE; ++s) bc += Bm[d * D_STATE + s] * Cm[d * D_STATE + s];
    const float Dd = Dv[d];

    const int l0 = c * CHUNK;
    size_t base  = ((size_t)(b * SEQ + l0)) * (2 * D_INNER) + d;
    size_t obase = ((size_t)(b * SEQ + l0)) * D_INNER + d;

    float xm1 = (l0 >= 1) ? g_XZ[base - 1 * 2 * D_INNER] : 0.f;
    float xm2 = (l0 >= 2) ? g_XZ[base - 2 * 2 * D_INNER] : 0.f;

    float run = 0.f;
    for (int i = 0; i < CHUNK; ++i) {
        float x0 = g_XZ[base];
        float zv = g_XZ[base + D_INNER];
        float pre = fmaf(w0, xm2, fmaf(w1, xm1, fmaf(w2, x0, cb)));
        float u  = pre / (1.f + expf(-pre));
        run += u;
        float sz = zv / (1.f + expf(-zv));
        g_T[obase]  = (run * bc + u * Dd) * sz;
        g_SZ[obase] = sz;
        xm2 = xm1; xm1 = x0;
        base  += 2 * D_INNER;
        obase += D_INNER;
    }
    g_CHS[(b * NCHUNK + c) * D_INNER + d] = run;
}

// ============ Phase B: exclusive scan of chunk sums, pre-mult by BC ============
__global__ void carry_kernel(const float* __restrict__ Bm, const float* __restrict__ Cm)
{
    int idx = blockIdx.x * blockDim.x + threadIdx.x;   // BATCH*D_INNER = 3072
    if (idx >= BATCH * D_INNER) return;
    int b = idx / D_INNER, d = idx % D_INNER;
    float bc = 0.f;
    #pragma unroll
    for (int s = 0; s < D_STATE; ++s) bc += Bm[d * D_STATE + s] * Cm[d * D_STATE + s];
    float car = 0.f;
    for (int c = 0; c < NCHUNK; ++c) {
        g_CBC[(b * NCHUNK + c) * D_INNER + d] = car * bc;
        car += g_CHS[(b * NCHUNK + c) * D_INNER + d];
    }
}

// ============ Phase C: t += carryBC * silz  (in place, float4) ============
__global__ void __launch_bounds__(256)
fix_kernel()
{
    int i = blockIdx.x * 256 + threadIdx.x;      // NTOK * 192 threads
    int m  = i / (D_INNER / 4);
    int d4 = i % (D_INNER / 4);
    int l = m & (SEQ - 1);
    int b = m >> 13;
    int c = l >> 8;                               // CHUNK=256
    float4 t  = ((float4*)g_T )[(size_t)m * (D_INNER / 4) + d4];
    float4 sz = ((float4*)g_SZ)[(size_t)m * (D_INNER / 4) + d4];
    float4 cb = ((const float4*)g_CBC)[(size_t)(b * NCHUNK + c) * (D_INNER / 4) + d4];
    t.x = fmaf(cb.x, sz.x, t.x);
    t.y = fmaf(cb.y, sz.y, t.y);
    t.z = fmaf(cb.z, sz.z, t.z);
    t.w = fmaf(cb.w, sz.w, t.w);
    ((float4*)g_T)[(size_t)m * (D_INNER / 4) + d4] = t;
}

// ============================ launch ============================
extern "C" void kernel_launch(void* const* d_in, const int* in_sizes, int n_in,
                              void* d_out, int out_size)
{
    const float* x      = (const float*)d_in[0];
    const float* W_in   = (const float*)d_in[1];
    const float* conv_w = (const float*)d_in[2];
    const float* conv_b = (const float*)d_in[3];
    const float* Bm     = (const float*)d_in[4];
    const float* Cm     = (const float*)d_in[5];
    const float* Dv     = (const float*)d_in[6];
    const float* W_out  = (const float*)d_in[7];
    float* out = (float*)d_out;

    // idempotent host-side attribute set (not a stream op; graph-capture safe)
    cudaFuncSetAttribute(gemm_tf32, cudaFuncAttributeMaxDynamicSharedMemorySize,
                         SMEM_FLOATS * 4);

    // GEMM1: XZ = X @ W_in   [32768,768] x [768,1536]
    dim3 g1((2 * D_INNER) / BN, NTOK / BM);
    gemm_tf32<<<g1, 256, SMEM_FLOATS * 4>>>(x, W_in, nullptr, NTOK, 2 * D_INNER, D_MODEL, 0, 1);

    // conv + silu + chunked scan
    scan_kernel<<<dim3(D_INNER / 256, NCHUNK, BATCH), 256>>>(conv_w, conv_b, Bm, Cm, Dv);
    carry_kernel<<<(BATCH * D_INNER + 255) / 256, 256>>>(Bm, Cm);
    fix_kernel<<<(NTOK * (D_INNER / 4)) / 256, 256>>>();

    // GEMM2: out = T @ W_out   [32768,768] x [768,768]
    dim3 g2(D_MODEL / BN, NTOK / BM);
    gemm_tf32<<<g2, 256, SMEM_FLOATS * 4>>>(nullptr, W_out, out, NTOK, D_MODEL, D_MODEL, 1, 0);
}

// round 7
// speedup vs baseline: 1.2842x; 1.2842x over previous
#include <cuda_runtime.h>
#include <cstdint>
#include <math.h>

#define D_MODEL 768
#define D_INNER 768
#define D_STATE 8
#define BATCH 4
#define SEQ 8192
#define NTOK (BATCH*SEQ)          /* 32768 */
#define CHUNK 256
#define NCHUNK (SEQ/CHUNK)        /* 32 */

// -------- scratch (allocation-free: __device__ globals) --------
__device__ float g_XZ[(size_t)NTOK * 2 * D_INNER];   // in_proj output
__device__ float g_T [(size_t)NTOK * D_INNER];       // (localcum*BC+u*D)*silz, fixed in place
__device__ float g_SZ[(size_t)NTOK * D_INNER];       // silu(z)
__device__ float g_CHS[BATCH * NCHUNK * D_INNER];
__device__ float g_CBC[BATCH * NCHUNK * D_INNER];

// ================= FP16 GEMM (mma.sync m16n8k16, fp32 accum) =================
// CTA tile 128x128, K-tile 32, double-buffered, 2 CTAs/SM.
// fp16 has the same 11-bit significand as tf32 -> identical rounding error,
// but m16n8k16 moves 2048 MACs/instr vs tf32's 1024 -> 2x HMMA throughput.
#define BM 128
#define BN 128
#define BK 32
#define APAD 40    // A row stride (floats): LDS.64 frag banks = 8*gid+2q, conflict-free
#define BPAD 132   // B row stride (floats): LDS.32 frag banks = 8q+gid,  conflict-free
#define A_ELE (BM * APAD)     /* 5120 floats */
#define B_ELE (BK * BPAD)     /* 4224 floats */
#define SMEM_FLOATS (2 * (A_ELE + B_ELE))   /* 18688 floats = 74752 B */

__device__ __forceinline__ uint32_t pack_f16x2(float lo, float hi) {
    uint32_t r;
    // cvt.f16x2: d[15:0] = cvt(second src), d[31:16] = cvt(first src)
    asm("cvt.rn.f16x2.f32 %0, %1, %2;" : "=r"(r) : "f"(hi), "f"(lo));
    return r;
}

__device__ __forceinline__ void mma_f16(float* d, const uint32_t* a, const uint32_t* b) {
    asm volatile(
        "mma.sync.aligned.m16n8k16.row.col.f32.f16.f16.f32 "
        "{%0,%1,%2,%3}, {%4,%5,%6,%7}, {%8,%9}, {%0,%1,%2,%3};"
        : "+f"(d[0]), "+f"(d[1]), "+f"(d[2]), "+f"(d[3])
        : "r"(a[0]), "r"(a[1]), "r"(a[2]), "r"(a[3]), "r"(b[0]), "r"(b[1]));
}

__device__ __forceinline__ void cp16(void* smem, const void* g) {
    uint32_t sa = (uint32_t)__cvta_generic_to_shared(smem);
    asm volatile("cp.async.cg.shared.global [%0], [%1], 16;" :: "r"(sa), "l"(g));
}

// asel: 0 -> A = Aext ; 1 -> A = g_T
// csel: 0 -> C = Cext ; 1 -> C = g_XZ
__global__ void __launch_bounds__(256, 2)
gemm_f16(const float* __restrict__ Aext, const float* __restrict__ Bmat,
         float* __restrict__ Cext, int M, int N, int K, int asel, int csel)
{
    const float* __restrict__ A = asel ? g_T : Aext;
    float* __restrict__ C = csel ? g_XZ : Cext;

    extern __shared__ __align__(16) float smem[];
    float* sA[2] = { smem,            smem + A_ELE };
    float* sB[2] = { smem + 2*A_ELE,  smem + 2*A_ELE + B_ELE };

    const int tid  = threadIdx.x;
    const int warp = tid >> 5;
    const int lane = tid & 31;
    const int warpM = warp >> 2;       // 0..1   (warp tile 64 x 32)
    const int warpN = warp & 3;        // 0..3
    const int gid = lane >> 2;         // 0..7
    const int q   = lane & 3;          // 0..3

    const int bm = blockIdx.y * BM;
    const int bn = blockIdx.x * BN;

    float acc[4][4][4];
    #pragma unroll
    for (int mt = 0; mt < 4; ++mt)
        #pragma unroll
        for (int nt = 0; nt < 4; ++nt)
            #pragma unroll
            for (int i = 0; i < 4; ++i) acc[mt][nt][i] = 0.f;

    const int KT = K / BK;

    // --- async tile load: stage s, k-tile kt. 2048 x 16B chunks, 8/thread ---
    auto load_stage = [&](int s, int kt) {
        const float* Ag = A    + (size_t)bm * K + kt * BK;
        const float* Bg = Bmat + (size_t)kt * BK * N + bn;
        #pragma unroll
        for (int it = 0; it < 4; ++it) {
            int idx = it * 256 + tid;           // 0..1023
            int ar  = idx >> 3;                 // 0..127
            int ac4 = idx & 7;                  // 0..7
            cp16(&sA[s][ar * APAD + ac4 * 4], Ag + (size_t)ar * K + ac4 * 4);
            int br  = idx >> 5;                 // 0..31
            int bc4 = idx & 31;                 // 0..31
            cp16(&sB[s][br * BPAD + bc4 * 4], Bg + (size_t)br * N + bc4 * 4);
        }
    };

    load_stage(0, 0);
    asm volatile("cp.async.commit_group;");

    for (int kt = 0; kt < KT; ++kt) {
        asm volatile("cp.async.wait_group 0;");
        __syncthreads();
        if (kt + 1 < KT) {
            load_stage((kt + 1) & 1, kt + 1);
            asm volatile("cp.async.commit_group;");
        }
        const float* __restrict__ sAp = sA[kt & 1];
        const float* __restrict__ sBp = sB[kt & 1];

        #pragma unroll
        for (int k16 = 0; k16 < BK / 16; ++k16) {
            const int kb = k16 * 16;
            uint32_t af[4][4], bf[4][2];
            #pragma unroll
            for (int mt = 0; mt < 4; ++mt) {
                int r0 = warpM * 64 + mt * 16 + gid;
                float2 p0 = *(const float2*)&sAp[(r0    ) * APAD + kb + 2*q    ];
                float2 p1 = *(const float2*)&sAp[(r0 + 8) * APAD + kb + 2*q    ];
                float2 p2 = *(const float2*)&sAp[(r0    ) * APAD + kb + 2*q + 8];
                float2 p3 = *(const float2*)&sAp[(r0 + 8) * APAD + kb + 2*q + 8];
                af[mt][0] = pack_f16x2(p0.x, p0.y);
                af[mt][1] = pack_f16x2(p1.x, p1.y);
                af[mt][2] = pack_f16x2(p2.x, p2.y);
                af[mt][3] = pack_f16x2(p3.x, p3.y);
            }
            #pragma unroll
            for (int nt = 0; nt < 4; ++nt) {
                int cn = warpN * 32 + nt * 8 + gid;
                bf[nt][0] = pack_f16x2(sBp[(kb + 2*q    ) * BPAD + cn],
                                       sBp[(kb + 2*q + 1) * BPAD + cn]);
                bf[nt][1] = pack_f16x2(sBp[(kb + 2*q + 8) * BPAD + cn],
                                       sBp[(kb + 2*q + 9) * BPAD + cn]);
            }
            #pragma unroll
            for (int mt = 0; mt < 4; ++mt)
                #pragma unroll
                for (int nt = 0; nt < 4; ++nt)
                    mma_f16(acc[mt][nt], af[mt], bf[nt]);
        }
    }

    // epilogue: direct stores (f32x2 per fragment pair)
    #pragma unroll
    for (int mt = 0; mt < 4; ++mt) {
        int gm = bm + warpM * 64 + mt * 16 + gid;
        #pragma unroll
        for (int nt = 0; nt < 4; ++nt) {
            int gn = bn + warpN * 32 + nt * 8 + q * 2;
            float2 v0 = make_float2(acc[mt][nt][0], acc[mt][nt][1]);
            float2 v1 = make_float2(acc[mt][nt][2], acc[mt][nt][3]);
            *(float2*)&C[(size_t)gm * N + gn]       = v0;
            *(float2*)&C[(size_t)(gm + 8) * N + gn] = v1;
        }
    }
}

// ============ Phase A: conv3 + silu + local cumsum per chunk ============
__global__ void __launch_bounds__(256)
scan_kernel(const float* __restrict__ conv_w, const float* __restrict__ conv_b,
            const float* __restrict__ Bm, const float* __restrict__ Cm,
            const float* __restrict__ Dv)
{
    const int d = blockIdx.x * 256 + threadIdx.x;
    const int c = blockIdx.y;
    const int b = blockIdx.z;

    const float w0 = conv_w[d * 3 + 0];
    const float w1 = conv_w[d * 3 + 1];
    const float w2 = conv_w[d * 3 + 2];
    const float cb = conv_b[d];
    float bc = 0.f;
    #pragma unroll
    for (int s = 0; s < D_STATE; ++s) bc += Bm[d * D_STATE + s] * Cm[d * D_STATE + s];
    const float Dd = Dv[d];

    const int l0 = c * CHUNK;
    size_t base  = ((size_t)(b * SEQ + l0)) * (2 * D_INNER) + d;
    size_t obase = ((size_t)(b * SEQ + l0)) * D_INNER + d;

    float xm1 = (l0 >= 1) ? g_XZ[base - 1 * 2 * D_INNER] : 0.f;
    float xm2 = (l0 >= 2) ? g_XZ[base - 2 * 2 * D_INNER] : 0.f;

    float run = 0.f;
    for (int i = 0; i < CHUNK; ++i) {
        float x0 = g_XZ[base];
        float zv = g_XZ[base + D_INNER];
        float pre = fmaf(w0, xm2, fmaf(w1, xm1, fmaf(w2, x0, cb)));
        float u  = pre / (1.f + expf(-pre));
        run += u;
        float sz = zv / (1.f + expf(-zv));
        g_T[obase]  = (run * bc + u * Dd) * sz;
        g_SZ[obase] = sz;
        xm2 = xm1; xm1 = x0;
        base  += 2 * D_INNER;
        obase += D_INNER;
    }
    g_CHS[(b * NCHUNK + c) * D_INNER + d] = run;
}

// ============ Phase B: exclusive scan of chunk sums, pre-mult by BC ============
__global__ void carry_kernel(const float* __restrict__ Bm, const float* __restrict__ Cm)
{
    int idx = blockIdx.x * blockDim.x + threadIdx.x;   // BATCH*D_INNER = 3072
    if (idx >= BATCH * D_INNER) return;
    int b = idx / D_INNER, d = idx % D_INNER;
    float bc = 0.f;
    #pragma unroll
    for (int s = 0; s < D_STATE; ++s) bc += Bm[d * D_STATE + s] * Cm[d * D_STATE + s];
    float car = 0.f;
    for (int c = 0; c < NCHUNK; ++c) {
        g_CBC[(b * NCHUNK + c) * D_INNER + d] = car * bc;
        car += g_CHS[(b * NCHUNK + c) * D_INNER + d];
    }
}

// ============ Phase C: t += carryBC * silz  (in place, float4) ============
__global__ void __launch_bounds__(256)
fix_kernel()
{
    int i = blockIdx.x * 256 + threadIdx.x;      // NTOK * 192 threads
    int m  = i / (D_INNER / 4);
    int d4 = i % (D_INNER / 4);
    int l = m & (SEQ - 1);
    int b = m >> 13;
    int c = l >> 8;                               // CHUNK=256
    float4 t  = ((float4*)g_T )[(size_t)m * (D_INNER / 4) + d4];
    float4 sz = ((float4*)g_SZ)[(size_t)m * (D_INNER / 4) + d4];
    float4 cb = ((const float4*)g_CBC)[(size_t)(b * NCHUNK + c) * (D_INNER / 4) + d4];
    t.x = fmaf(cb.x, sz.x, t.x);
    t.y = fmaf(cb.y, sz.y, t.y);
    t.z = fmaf(cb.z, sz.z, t.z);
    t.w = fmaf(cb.w, sz.w, t.w);
    ((float4*)g_T)[(size_t)m * (D_INNER / 4) + d4] = t;
}

// ============================ launch ============================
extern "C" void kernel_launch(void* const* d_in, const int* in_sizes, int n_in,
                              void* d_out, int out_size)
{
    const float* x      = (const float*)d_in[0];
    const float* W_in   = (const float*)d_in[1];
    const float* conv_w = (const float*)d_in[2];
    const float* conv_b = (const float*)d_in[3];
    const float* Bm     = (const float*)d_in[4];
    const float* Cm     = (const float*)d_in[5];
    const float* Dv     = (const float*)d_in[6];
    const float* W_out  = (const float*)d_in[7];
    float* out = (float*)d_out;

    // idempotent host-side attribute set (not a stream op; graph-capture safe)
    cudaFuncSetAttribute(gemm_f16, cudaFuncAttributeMaxDynamicSharedMemorySize,
                         SMEM_FLOATS * 4);

    // GEMM1: XZ = X @ W_in   [32768,768] x [768,1536]
    dim3 g1((2 * D_INNER) / BN, NTOK / BM);
    gemm_f16<<<g1, 256, SMEM_FLOATS * 4>>>(x, W_in, nullptr, NTOK, 2 * D_INNER, D_MODEL, 0, 1);

    // conv + silu + chunked scan
    scan_kernel<<<dim3(D_INNER / 256, NCHUNK, BATCH), 256>>>(conv_w, conv_b, Bm, Cm, Dv);
    carry_kernel<<<(BATCH * D_INNER + 255) / 256, 256>>>(Bm, Cm);
    fix_kernel<<<(NTOK * (D_INNER / 4)) / 256, 256>>>();

    // GEMM2: out = T @ W_out   [32768,768] x [768,768]
    dim3 g2(D_MODEL / BN, NTOK / BM);
    gemm_f16<<<g2, 256, SMEM_FLOATS * 4>>>(nullptr, W_out, out, NTOK, D_MODEL, D_MODEL, 1, 0);
}

// round 13
// speedup vs baseline: 1.8406x; 1.4333x over previous
#include <cuda_runtime.h>
#include <cuda_fp16.h>
#include <cstdint>
#include <math.h>

#define D_MODEL 768
#define D_INNER 768
#define D_STATE 8
#define BATCH 4
#define SEQ 8192
#define NTOK (BATCH*SEQ)          /* 32768 */
#define CHUNK 256
#define NCHUNK (SEQ/CHUNK)        /* 32 */
#define KDIM 768

// -------- scratch (allocation-free: __device__ globals) --------
__device__ float  g_XZ[(size_t)NTOK * 2 * D_INNER];   // in_proj output (fp32)
__device__ float  g_T [(size_t)NTOK * D_INNER];       // scan partial (fp32)
__device__ float  g_SZ[(size_t)NTOK * D_INNER];       // silu(z) (fp32)
__device__ __half g_Xh [(size_t)NTOK * D_MODEL];      // fp16 copy of x
__device__ __half g_Th [(size_t)NTOK * D_INNER];      // fp16 t (GEMM2 A operand)
__device__ __half g_Winh [(size_t)KDIM * 2 * D_INNER];
__device__ __half g_Wouth[(size_t)KDIM * D_INNER];
__device__ float  g_CHS[BATCH * NCHUNK * D_INNER];
__device__ float  g_CBC[BATCH * NCHUNK * D_INNER];

// ============== FP16 GEMM: fp16 smem + ldmatrix + m16n8k16 ==============
#define BM 128
#define BN 128
#define BK 32
#define NST 3
#define APITCH 40                    /* halves: 80B rows -> LDSM banks 20r mod 32 */
#define BPITCH 136                   /* halves: 272B rows -> LDSM banks 4r mod 32 */
#define A_TILE_H (BM * APITCH)       /* 5120 halves = 10240 B */
#define B_TILE_H (BK * BPITCH)       /* 4352 halves =  8704 B */
#define STAGE_H  (A_TILE_H + B_TILE_H)
#define STAGE_B  (STAGE_H * 2)       /* 18944 B */
#define SMEM_B   (NST * STAGE_B)     /* 56832 B */

__device__ __forceinline__ void mma_f16(float* d, const uint32_t* a, const uint32_t* b) {
    asm volatile(
        "mma.sync.aligned.m16n8k16.row.col.f32.f16.f16.f32 "
        "{%0,%1,%2,%3}, {%4,%5,%6,%7}, {%8,%9}, {%0,%1,%2,%3};"
        : "+f"(d[0]), "+f"(d[1]), "+f"(d[2]), "+f"(d[3])
        : "r"(a[0]), "r"(a[1]), "r"(a[2]), "r"(a[3]), "r"(b[0]), "r"(b[1]));
}
__device__ __forceinline__ void cp16(void* smem, const void* g) {
    uint32_t sa = (uint32_t)__cvta_generic_to_shared(smem);
    asm volatile("cp.async.cg.shared.global [%0], [%1], 16;" :: "r"(sa), "l"(g));
}
__device__ __forceinline__ void ldsm_x4(uint32_t* r, uint32_t addr) {
    asm volatile("ldmatrix.sync.aligned.m8n8.x4.shared.b16 {%0,%1,%2,%3}, [%4];"
        : "=r"(r[0]), "=r"(r[1]), "=r"(r[2]), "=r"(r[3]) : "r"(addr));
}
__device__ __forceinline__ void ldsm_x4_t(uint32_t* r, uint32_t addr) {
    asm volatile("ldmatrix.sync.aligned.m8n8.x4.trans.shared.b16 {%0,%1,%2,%3}, [%4];"
        : "=r"(r[0]), "=r"(r[1]), "=r"(r[2]), "=r"(r[3]) : "r"(addr));
}

// sel 0: C=g_XZ = g_Xh @ g_Winh   (N=1536)
// sel 1: C=Cext = g_Th @ g_Wouth  (N=768)
__global__ void __launch_bounds__(256, 2)
gemm_h(float* __restrict__ Cext, int N, int sel)
{
    const __half* __restrict__ Ah = sel ? g_Th    : g_Xh;
    const __half* __restrict__ Bh = sel ? g_Wouth : g_Winh;
    float* __restrict__ C         = sel ? Cext    : g_XZ;

    extern __shared__ __align__(16) __half hsm[];
    const uint32_t smem_u = (uint32_t)__cvta_generic_to_shared(hsm);

    const int tid  = threadIdx.x;
    const int warp = tid >> 5;
    const int lane = tid & 31;
    const int warpM = warp >> 2;           // 0..1  (warp tile 64x32)
    const int warpN = warp & 3;            // 0..3
    const int gid = lane >> 2;
    const int q   = lane & 3;

    // ldmatrix per-lane source rows/cols
    const int lrow = lane & 7;
    const int sub  = lane >> 3;
    const int xrow = lrow + (sub & 1) * 8;     // 0..15
    const int xcol = (sub >> 1) * 8;           // 0 or 8

    const int bm = blockIdx.y * BM;
    const int bn = blockIdx.x * BN;
    const int KT = KDIM / BK;                  // 24

    float acc[4][4][4];
    #pragma unroll
    for (int mt = 0; mt < 4; ++mt)
        #pragma unroll
        for (int nt = 0; nt < 4; ++nt)
            #pragma unroll
            for (int i = 0; i < 4; ++i) acc[mt][nt][i] = 0.f;

    // --- stage loader: A 128x4 chunks + B 32x16 chunks, 512 idx x 2 cp each ---
    auto load_stage = [&](int s, int kt) {
        __half* sa = hsm + s * STAGE_H;
        __half* sb = sa + A_TILE_H;
        const __half* Ag = Ah + (size_t)bm * KDIM + kt * BK;
        const __half* Bg = Bh + (size_t)(kt * BK) * N + bn;
        #pragma unroll
        for (int it = 0; it < 2; ++it) {
            int idx = it * 256 + tid;            // 0..511
            int ar = idx >> 2, ac = idx & 3;     // A: 128 rows x 4 chunks(8h)
            cp16(sa + ar * APITCH + ac * 8, Ag + (size_t)ar * KDIM + ac * 8);
            int br = idx >> 4, bc = idx & 15;    // B: 32 rows x 16 chunks(8h)
            cp16(sb + br * BPITCH + bc * 8, Bg + (size_t)br * N + bc * 8);
        }
    };

    load_stage(0, 0);
    asm volatile("cp.async.commit_group;");
    load_stage(1, 1);
    asm volatile("cp.async.commit_group;");

    for (int kt = 0; kt < KT; ++kt) {
        // guarantee stage kt has landed: on the last iteration no newer group
        // exists, so a full drain is required.
        if (kt + 1 < KT) asm volatile("cp.async.wait_group 1;");
        else             asm volatile("cp.async.wait_group 0;");
        __syncthreads();
        if (kt + 2 < KT) {
            load_stage((kt + 2) % NST, kt + 2);
            asm volatile("cp.async.commit_group;");
        }
        const int s = kt % NST;
        const uint32_t aBase = smem_u + s * STAGE_B;
        const uint32_t bBase = aBase + A_TILE_H * 2;

        #pragma unroll
        for (int k16 = 0; k16 < BK / 16; ++k16) {
            const int kb = k16 * 16;
            uint32_t af[4][4], bf[2][4];
            #pragma unroll
            for (int mt = 0; mt < 4; ++mt)
                ldsm_x4(af[mt], aBase +
                    2u * ((warpM * 64 + mt * 16 + xrow) * APITCH + kb + xcol));
            #pragma unroll
            for (int bt = 0; bt < 2; ++bt)
                ldsm_x4_t(bf[bt], bBase +
                    2u * ((kb + xrow) * BPITCH + warpN * 32 + bt * 16 + xcol));
            #pragma unroll
            for (int mt = 0; mt < 4; ++mt)
                #pragma unroll
                for (int nt = 0; nt < 4; ++nt)
                    mma_f16(acc[mt][nt], af[mt], &bf[nt >> 1][(nt & 1) * 2]);
        }
    }

    // epilogue: direct fp32 stores
    #pragma unroll
    for (int mt = 0; mt < 4; ++mt) {
        int gm = bm + warpM * 64 + mt * 16 + gid;
        #pragma unroll
        for (int nt = 0; nt < 4; ++nt) {
            int gn = bn + warpN * 32 + nt * 8 + q * 2;
            *(float2*)&C[(size_t)gm * N + gn]       = make_float2(acc[mt][nt][0], acc[mt][nt][1]);
            *(float2*)&C[(size_t)(gm + 8) * N + gn] = make_float2(acc[mt][nt][2], acc[mt][nt][3]);
        }
    }
}

// ================= fp32 -> fp16 bulk convert (8 elems/thread) =================
__global__ void __launch_bounds__(256)
f2h_kernel(const float* __restrict__ s, __half* __restrict__ d)
{
    size_t i = (size_t)blockIdx.x * 256 + threadIdx.x;
    float4 a = ((const float4*)s)[2 * i];
    float4 b = ((const float4*)s)[2 * i + 1];
    __half2 h0 = __floats2half2_rn(a.x, a.y);
    __half2 h1 = __floats2half2_rn(a.z, a.w);
    __half2 h2 = __floats2half2_rn(b.x, b.y);
    __half2 h3 = __floats2half2_rn(b.z, b.w);
    ((uint4*)d)[i] = make_uint4(*(uint32_t*)&h0, *(uint32_t*)&h1,
                                *(uint32_t*)&h2, *(uint32_t*)&h3);
}

// ============ Phase A: conv3 + silu + local cumsum per chunk ============
__global__ void __launch_bounds__(256)
scan_kernel(const float* __restrict__ conv_w, const float* __restrict__ conv_b,
            const float* __restrict__ Bm, const float* __restrict__ Cm,
            const float* __restrict__ Dv)
{
    const int d = blockIdx.x * 256 + threadIdx.x;
    const int c = blockIdx.y;
    const int b = blockIdx.z;

    const float w0 = conv_w[d * 3 + 0];
    const float w1 = conv_w[d * 3 + 1];
    const float w2 = conv_w[d * 3 + 2];
    const float cb = conv_b[d];
    float bc = 0.f;
    #pragma unroll
    for (int s = 0; s < D_STATE; ++s) bc += Bm[d * D_STATE + s] * Cm[d * D_STATE + s];
    const float Dd = Dv[d];

    const int l0 = c * CHUNK;
    size_t base  = ((size_t)(b * SEQ + l0)) * (2 * D_INNER) + d;
    size_t obase = ((size_t)(b * SEQ + l0)) * D_INNER + d;

    float xm1 = (l0 >= 1) ? g_XZ[base - 1 * 2 * D_INNER] : 0.f;
    float xm2 = (l0 >= 2) ? g_XZ[base - 2 * 2 * D_INNER] : 0.f;

    float run = 0.f;
    for (int i = 0; i < CHUNK; ++i) {
        float x0 = g_XZ[base];
        float zv = g_XZ[base + D_INNER];
        float pre = fmaf(w0, xm2, fmaf(w1, xm1, fmaf(w2, x0, cb)));
        float u  = pre / (1.f + expf(-pre));
        run += u;
        float sz = zv / (1.f + expf(-zv));
        g_T[obase]  = (run * bc + u * Dd) * sz;
        g_SZ[obase] = sz;
        xm2 = xm1; xm1 = x0;
        base  += 2 * D_INNER;
        obase += D_INNER;
    }
    g_CHS[(b * NCHUNK + c) * D_INNER + d] = run;
}

// ============ Phase B: exclusive scan of chunk sums, pre-mult by BC ============
__global__ void carry_kernel(const float* __restrict__ Bm, const float* __restrict__ Cm)
{
    int idx = blockIdx.x * blockDim.x + threadIdx.x;   // BATCH*D_INNER = 3072
    if (idx >= BATCH * D_INNER) return;
    int b = idx / D_INNER, d = idx % D_INNER;
    float bc = 0.f;
    #pragma unroll
    for (int s = 0; s < D_STATE; ++s) bc += Bm[d * D_STATE + s] * Cm[d * D_STATE + s];
    float car = 0.f;
    for (int c = 0; c < NCHUNK; ++c) {
        g_CBC[(b * NCHUNK + c) * D_INNER + d] = car * bc;
        car += g_CHS[(b * NCHUNK + c) * D_INNER + d];
    }
}

// ====== Phase C: g_Th = fp16(t + carryBC * silz)  (fp16 out for GEMM2) ======
__global__ void __launch_bounds__(256)
fix_kernel()
{
    int i = blockIdx.x * 256 + threadIdx.x;      // NTOK * 192 threads
    int m  = i / (D_INNER / 4);
    int d4 = i % (D_INNER / 4);
    int l = m & (SEQ - 1);
    int b = m >> 13;
    int c = l >> 8;                               // CHUNK=256
    float4 t  = ((float4*)g_T )[(size_t)m * (D_INNER / 4) + d4];
    float4 sz = ((float4*)g_SZ)[(size_t)m * (D_INNER / 4) + d4];
    float4 cb = ((const float4*)g_CBC)[(size_t)(b * NCHUNK + c) * (D_INNER / 4) + d4];
    t.x = fmaf(cb.x, sz.x, t.x);
    t.y = fmaf(cb.y, sz.y, t.y);
    t.z = fmaf(cb.z, sz.z, t.z);
    t.w = fmaf(cb.w, sz.w, t.w);
    __half2 h0 = __floats2half2_rn(t.x, t.y);
    __half2 h1 = __floats2half2_rn(t.z, t.w);
    ((uint2*)g_Th)[(size_t)m * (D_INNER / 4) + d4] =
        make_uint2(*(uint32_t*)&h0, *(uint32_t*)&h1);
}

// ============================ launch ============================
extern "C" void kernel_launch(void* const* d_in, const int* in_sizes, int n_in,
                              void* d_out, int out_size)
{
    const float* x      = (const float*)d_in[0];
    const float* W_in   = (const float*)d_in[1];
    const float* conv_w = (const float*)d_in[2];
    const float* conv_b = (const float*)d_in[3];
    const float* Bm     = (const float*)d_in[4];
    const float* Cm     = (const float*)d_in[5];
    const float* Dv     = (const float*)d_in[6];
    const float* W_out  = (const float*)d_in[7];
    float* out = (float*)d_out;

    // idempotent host-side attribute set (graph-capture safe)
    cudaFuncSetAttribute(gemm_h, cudaFuncAttributeMaxDynamicSharedMemorySize, SMEM_B);

    __half* d_Xh;    cudaGetSymbolAddress((void**)&d_Xh,    g_Xh);
    __half* d_Winh;  cudaGetSymbolAddress((void**)&d_Winh,  g_Winh);
    __half* d_Wouth; cudaGetSymbolAddress((void**)&d_Wouth, g_Wouth);

    // fp16 copies of GEMM operands
    f2h_kernel<<<(NTOK * D_MODEL / 8) / 256, 256>>>(x, d_Xh);
    f2h_kernel<<<(KDIM * 2 * D_INNER / 8) / 256, 256>>>(W_in, d_Winh);
    f2h_kernel<<<(KDIM * D_INNER / 8) / 256, 256>>>(W_out, d_Wouth);

    // GEMM1: g_XZ = Xh @ Winh   [32768,768] x [768,1536]
    gemm_h<<<dim3((2 * D_INNER) / BN, NTOK / BM), 256, SMEM_B>>>(nullptr, 2 * D_INNER, 0);

    // conv + silu + chunked scan (fp32), carry fix emits fp16 T
    scan_kernel<<<dim3(D_INNER / 256, NCHUNK, BATCH), 256>>>(conv_w, conv_b, Bm, Cm, Dv);
    carry_kernel<<<(BATCH * D_INNER + 255) / 256, 256>>>(Bm, Cm);
    fix_kernel<<<(NTOK * (D_INNER / 4)) / 256, 256>>>();

    // GEMM2: out = Th @ Wouth   [32768,768] x [768,768]
    gemm_h<<<dim3(D_MODEL / BN, NTOK / BM), 256, SMEM_B>>>(out, D_MODEL, 1);
}

// round 14
// speedup vs baseline: 1.8583x; 1.0096x over previous
#include <cuda_runtime.h>
#include <cuda_fp16.h>
#include <cstdint>
#include <math.h>

#define D_MODEL 768
#define D_INNER 768
#define D_STATE 8
#define BATCH 4
#define SEQ 8192
#define NTOK (BATCH*SEQ)          /* 32768 */
#define CHUNK 256
#define NCHUNK (SEQ/CHUNK)        /* 32 */
#define KDIM 768

// -------- scratch (allocation-free: __device__ globals) --------
__device__ float  g_XZ[(size_t)NTOK * 2 * D_INNER];   // in_proj output (fp32)
__device__ float  g_T [(size_t)NTOK * D_INNER];       // scan partial (fp32)
__device__ float  g_SZ[(size_t)NTOK * D_INNER];       // silu(z) (fp32)
__device__ __half g_Xh [(size_t)NTOK * D_MODEL];      // fp16 copy of x
__device__ __half g_Th [(size_t)NTOK * D_INNER];      // fp16 t (GEMM2 A operand)
__device__ __half g_Winh [(size_t)KDIM * 2 * D_INNER];
__device__ __half g_Wouth[(size_t)KDIM * D_INNER];
__device__ float  g_CHS[BATCH * NCHUNK * D_INNER];
__device__ float  g_CBC[BATCH * NCHUNK * D_INNER];

// ============== FP16 GEMM: fp16 smem + ldmatrix + m16n8k16 ==============
// BK=64: halves the barrier count vs BK=32; 4 k16-steps per stage keep the
// tensor pipe covered across the LDSM bursts.
#define BM 128
#define BN 128
#define BK 64
#define NST 3
#define APITCH 72                    /* halves: 144B rows -> LDSM banks 4r mod 32 */
#define BPITCH 136                   /* halves: 272B rows -> LDSM banks 4r mod 32 */
#define A_TILE_H (BM * APITCH)       /* 9216 halves = 18432 B */
#define B_TILE_H (BK * BPITCH)       /* 8704 halves = 17408 B */
#define STAGE_H  (A_TILE_H + B_TILE_H)
#define STAGE_B  (STAGE_H * 2)       /* 35840 B */
#define SMEM_B   (NST * STAGE_B)     /* 107520 B */

__device__ __forceinline__ void mma_f16(float* d, const uint32_t* a, const uint32_t* b) {
    asm volatile(
        "mma.sync.aligned.m16n8k16.row.col.f32.f16.f16.f32 "
        "{%0,%1,%2,%3}, {%4,%5,%6,%7}, {%8,%9}, {%0,%1,%2,%3};"
        : "+f"(d[0]), "+f"(d[1]), "+f"(d[2]), "+f"(d[3])
        : "r"(a[0]), "r"(a[1]), "r"(a[2]), "r"(a[3]), "r"(b[0]), "r"(b[1]));
}
__device__ __forceinline__ void cp16(void* smem, const void* g) {
    uint32_t sa = (uint32_t)__cvta_generic_to_shared(smem);
    asm volatile("cp.async.cg.shared.global [%0], [%1], 16;" :: "r"(sa), "l"(g));
}
__device__ __forceinline__ void ldsm_x4(uint32_t* r, uint32_t addr) {
    asm volatile("ldmatrix.sync.aligned.m8n8.x4.shared.b16 {%0,%1,%2,%3}, [%4];"
        : "=r"(r[0]), "=r"(r[1]), "=r"(r[2]), "=r"(r[3]) : "r"(addr));
}
__device__ __forceinline__ void ldsm_x4_t(uint32_t* r, uint32_t addr) {
    asm volatile("ldmatrix.sync.aligned.m8n8.x4.trans.shared.b16 {%0,%1,%2,%3}, [%4];"
        : "=r"(r[0]), "=r"(r[1]), "=r"(r[2]), "=r"(r[3]) : "r"(addr));
}

// sel 0: C=g_XZ = g_Xh @ g_Winh   (N=1536)
// sel 1: C=Cext = g_Th @ g_Wouth  (N=768)
__global__ void __launch_bounds__(256, 2)
gemm_h(float* __restrict__ Cext, int N, int sel)
{
    const __half* __restrict__ Ah = sel ? g_Th    : g_Xh;
    const __half* __restrict__ Bh = sel ? g_Wouth : g_Winh;
    float* __restrict__ C         = sel ? Cext    : g_XZ;

    extern __shared__ __align__(16) __half hsm[];
    const uint32_t smem_u = (uint32_t)__cvta_generic_to_shared(hsm);

    const int tid  = threadIdx.x;
    const int warp = tid >> 5;
    const int lane = tid & 31;
    const int warpM = warp >> 2;           // 0..1  (warp tile 64x32)
    const int warpN = warp & 3;            // 0..3
    const int gid = lane >> 2;
    const int q   = lane & 3;

    // ldmatrix per-lane source rows/cols
    const int lrow = lane & 7;
    const int sub  = lane >> 3;
    const int xrow = lrow + (sub & 1) * 8;     // 0..15
    const int xcol = (sub >> 1) * 8;           // 0 or 8

    const int bm = blockIdx.y * BM;
    const int bn = blockIdx.x * BN;
    const int KT = KDIM / BK;                  // 12

    float acc[4][4][4];
    #pragma unroll
    for (int mt = 0; mt < 4; ++mt)
        #pragma unroll
        for (int nt = 0; nt < 4; ++nt)
            #pragma unroll
            for (int i = 0; i < 4; ++i) acc[mt][nt][i] = 0.f;

    // --- stage loader: A 128x8 chunks + B 64x16 chunks (8 halves each) ---
    auto load_stage = [&](int s, int kt) {
        __half* sa = hsm + s * STAGE_H;
        __half* sb = sa + A_TILE_H;
        const __half* Ag = Ah + (size_t)bm * KDIM + kt * BK;
        const __half* Bg = Bh + (size_t)(kt * BK) * N + bn;
        #pragma unroll
        for (int it = 0; it < 4; ++it) {
            int idx = it * 256 + tid;            // 0..1023
            int ar = idx >> 3, ac = idx & 7;     // A: 128 rows x 8 chunks
            cp16(sa + ar * APITCH + ac * 8, Ag + (size_t)ar * KDIM + ac * 8);
            int br = idx >> 4, bc = idx & 15;    // B: 64 rows x 16 chunks
            cp16(sb + br * BPITCH + bc * 8, Bg + (size_t)br * N + bc * 8);
        }
    };

    load_stage(0, 0);
    asm volatile("cp.async.commit_group;");
    load_stage(1, 1);
    asm volatile("cp.async.commit_group;");

    for (int kt = 0; kt < KT; ++kt) {
        // guarantee stage kt landed; final iteration needs a full drain.
        if (kt + 1 < KT) asm volatile("cp.async.wait_group 1;");
        else             asm volatile("cp.async.wait_group 0;");
        __syncthreads();
        if (kt + 2 < KT) {
            load_stage((kt + 2) % NST, kt + 2);
            asm volatile("cp.async.commit_group;");
        }
        const int s = kt % NST;
        const uint32_t aBase = smem_u + s * STAGE_B;
        const uint32_t bBase = aBase + A_TILE_H * 2;

        #pragma unroll
        for (int k16 = 0; k16 < BK / 16; ++k16) {
            const int kb = k16 * 16;
            uint32_t af[4][4], bf[2][4];
            #pragma unroll
            for (int mt = 0; mt < 4; ++mt)
                ldsm_x4(af[mt], aBase +
                    2u * ((warpM * 64 + mt * 16 + xrow) * APITCH + kb + xcol));
            #pragma unroll
            for (int bt = 0; bt < 2; ++bt)
                ldsm_x4_t(bf[bt], bBase +
                    2u * ((kb + xrow) * BPITCH + warpN * 32 + bt * 16 + xcol));
            #pragma unroll
            for (int mt = 0; mt < 4; ++mt)
                #pragma unroll
                for (int nt = 0; nt < 4; ++nt)
                    mma_f16(acc[mt][nt], af[mt], &bf[nt >> 1][(nt & 1) * 2]);
        }
    }

    // epilogue: direct fp32 stores
    #pragma unroll
    for (int mt = 0; mt < 4; ++mt) {
        int gm = bm + warpM * 64 + mt * 16 + gid;
        #pragma unroll
        for (int nt = 0; nt < 4; ++nt) {
            int gn = bn + warpN * 32 + nt * 8 + q * 2;
            *(float2*)&C[(size_t)gm * N + gn]       = make_float2(acc[mt][nt][0], acc[mt][nt][1]);
            *(float2*)&C[(size_t)(gm + 8) * N + gn] = make_float2(acc[mt][nt][2], acc[mt][nt][3]);
        }
    }
}

// ================= fp32 -> fp16 bulk convert (8 elems/thread) =================
__global__ void __launch_bounds__(256)
f2h_kernel(const float* __restrict__ s, __half* __restrict__ d)
{
    size_t i = (size_t)blockIdx.x * 256 + threadIdx.x;
    float4 a = ((const float4*)s)[2 * i];
    float4 b = ((const float4*)s)[2 * i + 1];
    __half2 h0 = __floats2half2_rn(a.x, a.y);
    __half2 h1 = __floats2half2_rn(a.z, a.w);
    __half2 h2 = __floats2half2_rn(b.x, b.y);
    __half2 h3 = __floats2half2_rn(b.z, b.w);
    ((uint4*)d)[i] = make_uint4(*(uint32_t*)&h0, *(uint32_t*)&h1,
                                *(uint32_t*)&h2, *(uint32_t*)&h3);
}

// ============ Phase A: conv3 + silu + local cumsum per chunk ============
__global__ void __launch_bounds__(256)
scan_kernel(const float* __restrict__ conv_w, const float* __restrict__ conv_b,
            const float* __restrict__ Bm, const float* __restrict__ Cm,
            const float* __restrict__ Dv)
{
    const int d = blockIdx.x * 256 + threadIdx.x;
    const int c = blockIdx.y;
    const int b = blockIdx.z;

    const float w0 = conv_w[d * 3 + 0];
    const float w1 = conv_w[d * 3 + 1];
    const float w2 = conv_w[d * 3 + 2];
    const float cb = conv_b[d];
    float bc = 0.f;
    #pragma unroll
    for (int s = 0; s < D_STATE; ++s) bc += Bm[d * D_STATE + s] * Cm[d * D_STATE + s];
    const float Dd = Dv[d];

    const int l0 = c * CHUNK;
    size_t base  = ((size_t)(b * SEQ + l0)) * (2 * D_INNER) + d;
    size_t obase = ((size_t)(b * SEQ + l0)) * D_INNER + d;

    float xm1 = (l0 >= 1) ? g_XZ[base - 1 * 2 * D_INNER] : 0.f;
    float xm2 = (l0 >= 2) ? g_XZ[base - 2 * 2 * D_INNER] : 0.f;

    float run = 0.f;
    for (int i = 0; i < CHUNK; ++i) {
        float x0 = g_XZ[base];
        float zv = g_XZ[base + D_INNER];
        float pre = fmaf(w0, xm2, fmaf(w1, xm1, fmaf(w2, x0, cb)));
        float u  = pre / (1.f + expf(-pre));
        run += u;
        float sz = zv / (1.f + expf(-zv));
        g_T[obase]  = (run * bc + u * Dd) * sz;
        g_SZ[obase] = sz;
        xm2 = xm1; xm1 = x0;
        base  += 2 * D_INNER;
        obase += D_INNER;
    }
    g_CHS[(b * NCHUNK + c) * D_INNER + d] = run;
}

// ============ Phase B: exclusive scan of chunk sums, pre-mult by BC ============
__global__ void carry_kernel(const float* __restrict__ Bm, const float* __restrict__ Cm)
{
    int idx = blockIdx.x * blockDim.x + threadIdx.x;   // BATCH*D_INNER = 3072
    if (idx >= BATCH * D_INNER) return;
    int b = idx / D_INNER, d = idx % D_INNER;
    float bc = 0.f;
    #pragma unroll
    for (int s = 0; s < D_STATE; ++s) bc += Bm[d * D_STATE + s] * Cm[d * D_STATE + s];
    float car = 0.f;
    for (int c = 0; c < NCHUNK; ++c) {
        g_CBC[(b * NCHUNK + c) * D_INNER + d] = car * bc;
        car += g_CHS[(b * NCHUNK + c) * D_INNER + d];
    }
}

// ====== Phase C: g_Th = fp16(t + carryBC * silz)  (fp16 out for GEMM2) ======
__global__ void __launch_bounds__(256)
fix_kernel()
{
    int i = blockIdx.x * 256 + threadIdx.x;      // NTOK * 192 threads
    int m  = i / (D_INNER / 4);
    int d4 = i % (D_INNER / 4);
    int l = m & (SEQ - 1);
    int b = m >> 13;
    int c = l >> 8;                               // CHUNK=256
    float4 t  = ((float4*)g_T )[(size_t)m * (D_INNER / 4) + d4];
    float4 sz = ((float4*)g_SZ)[(size_t)m * (D_INNER / 4) + d4];
    float4 cb = ((const float4*)g_CBC)[(size_t)(b * NCHUNK + c) * (D_INNER / 4) + d4];
    t.x = fmaf(cb.x, sz.x, t.x);
    t.y = fmaf(cb.y, sz.y, t.y);
    t.z = fmaf(cb.z, sz.z, t.z);
    t.w = fmaf(cb.w, sz.w, t.w);
    __half2 h0 = __floats2half2_rn(t.x, t.y);
    __half2 h1 = __floats2half2_rn(t.z, t.w);
    ((uint2*)g_Th)[(size_t)m * (D_INNER / 4) + d4] =
        make_uint2(*(uint32_t*)&h0, *(uint32_t*)&h1);
}

// ============================ launch ============================
extern "C" void kernel_launch(void* const* d_in, const int* in_sizes, int n_in,
                              void* d_out, int out_size)
{
    const float* x      = (const float*)d_in[0];
    const float* W_in   = (const float*)d_in[1];
    const float* conv_w = (const float*)d_in[2];
    const float* conv_b = (const float*)d_in[3];
    const float* Bm     = (const float*)d_in[4];
    const float* Cm     = (const float*)d_in[5];
    const float* Dv     = (const float*)d_in[6];
    const float* W_out  = (const float*)d_in[7];
    float* out = (float*)d_out;

    // idempotent host-side attribute set (graph-capture safe)
    cudaFuncSetAttribute(gemm_h, cudaFuncAttributeMaxDynamicSharedMemorySize, SMEM_B);

    __half* d_Xh;    cudaGetSymbolAddress((void**)&d_Xh,    g_Xh);
    __half* d_Winh;  cudaGetSymbolAddress((void**)&d_Winh,  g_Winh);
    __half* d_Wouth; cudaGetSymbolAddress((void**)&d_Wouth, g_Wouth);

    // fp16 copies of GEMM operands
    f2h_kernel<<<(NTOK * D_MODEL / 8) / 256, 256>>>(x, d_Xh);
    f2h_kernel<<<(KDIM * 2 * D_INNER / 8) / 256, 256>>>(W_in, d_Winh);
    f2h_kernel<<<(KDIM * D_INNER / 8) / 256, 256>>>(W_out, d_Wouth);

    // GEMM1: g_XZ = Xh @ Winh   [32768,768] x [768,1536]
    gemm_h<<<dim3((2 * D_INNER) / BN, NTOK / BM), 256, SMEM_B>>>(nullptr, 2 * D_INNER, 0);

    // conv + silu + chunked scan (fp32), carry fix emits fp16 T
    scan_kernel<<<dim3(D_INNER / 256, NCHUNK, BATCH), 256>>>(conv_w, conv_b, Bm, Cm, Dv);
    carry_kernel<<<(BATCH * D_INNER + 255) / 256, 256>>>(Bm, Cm);
    fix_kernel<<<(NTOK * (D_INNER / 4)) / 256, 256>>>();

    // GEMM2: out = Th @ Wouth   [32768,768] x [768,768]
    gemm_h<<<dim3(D_MODEL / BN, NTOK / BM), 256, SMEM_B>>>(out, D_MODEL, 1);
}